// round 7
// baseline (speedup 1.0000x reference)
#include <cuda_runtime.h>
#include <cuda_bf16.h>
#include <cstdint>

// ---------------------------------------------------------------------------
// ArcFace fused, warp-MMA edition (base sm_103 target: mma.sync + ldmatrix;
// tcgen05 is unavailable because the harness compiles for plain sm_103).
//   out[0*B*C..) cos, out[1*B*C..) marginal (gt patched inline),
//   out[2*B*C..) innerproduct.   B=256, D=128, C=100000.
// dot = f_hi.w_hi + f_hi.w_lo + f_lo.w_hi  (split-bf16 ~ fp32 to ~1e-5 rel)
// ---------------------------------------------------------------------------

static __device__ __constant__ float kCOS_M  = 0.8775825618903728f;   // cos(0.5)
static __device__ __constant__ float kSIN_M  = 0.4794255386042030f;   // sin(0.5)
static __device__ __constant__ float kTHRESH = -0.8775825618903728f;  // -cos(0.5)
#define K_SCALE 35.0f

__device__ float g_invnf[1024];
__device__ float g_invnw[100608];

// ---------------------------------------------------------------------------
__device__ __forceinline__ uint32_t smem_u32(const void* p) {
    uint32_t a;
    asm("{ .reg .u64 t; cvta.to.shared.u64 t, %1; cvt.u32.u64 %0, t; }"
        : "=r"(a) : "l"(p));
    return a;
}
__device__ __forceinline__ void ldsm4(uint32_t* r, uint32_t addr) {
    asm volatile("ldmatrix.sync.aligned.m8n8.x4.shared.b16 {%0,%1,%2,%3}, [%4];"
                 : "=r"(r[0]), "=r"(r[1]), "=r"(r[2]), "=r"(r[3]) : "r"(addr));
}
__device__ __forceinline__ void mma16816(float* c, const uint32_t* a,
                                         uint32_t b0, uint32_t b1) {
    asm volatile(
        "mma.sync.aligned.m16n8k16.row.col.f32.bf16.bf16.f32 "
        "{%0,%1,%2,%3}, {%4,%5,%6,%7}, {%8,%9}, {%0,%1,%2,%3};"
        : "+f"(c[0]), "+f"(c[1]), "+f"(c[2]), "+f"(c[3])
        : "r"(a[0]), "r"(a[1]), "r"(a[2]), "r"(a[3]), "r"(b0), "r"(b1));
}

// swizzled byte offset inside a 128-row x 128-bf16 tile (256B rows, 16B-chunk
// XOR swizzle -> conflict-free STS.32 and LDSM).  pk = bf16-pair index 0..63.
__device__ __forceinline__ uint32_t sw_off(uint32_t row, uint32_t pk) {
    return row * 256u + ((((pk >> 2) ^ (row & 7)) << 4)) + (pk & 3) * 4u;
}
// ldmatrix row address: row r, 16B chunk c (0..15)
__device__ __forceinline__ uint32_t sw_row(uint32_t r, uint32_t c) {
    return r * 256u + ((c ^ (r & 7)) << 4);
}

// smem layout: 4 bf16 tiles of 32KB + invw[128]
#define OF_FHI 0
#define OF_FLO 32768
#define OF_WHI 65536
#define OF_WLO 98304
#define OF_INVW 131072
#define SMEM_TOTAL (131072 + 512)

// ---------------------------------------------------------------------------
__global__ void norm_kernel(const float* __restrict__ x, int rows, int which) {
    int row = blockIdx.x * blockDim.y + threadIdx.y;
    if (row >= rows) return;
    int lane = threadIdx.x;
    float4 v = *reinterpret_cast<const float4*>(x + (size_t)row * 128 + lane * 4);
    float s = v.x * v.x + v.y * v.y + v.z * v.z + v.w * v.w;
#pragma unroll
    for (int o = 16; o > 0; o >>= 1) s += __shfl_xor_sync(0xffffffffu, s, o);
    if (lane == 0) {
        float inv = rsqrtf(s);
        if (which) g_invnw[row] = inv; else g_invnf[row] = inv;
    }
}

// ---------------------------------------------------------------------------
__global__ __launch_bounds__(256, 1)
void arcface_mma(const float* __restrict__ feat, const float* __restrict__ W,
                 const int* __restrict__ label, float* __restrict__ out,
                 int B, int C) {
    extern __shared__ __align__(1024) char smem[];
    const uint32_t sb = smem_u32(smem);
    float* invw_s = reinterpret_cast<float*>(smem + OF_INVW);

    const int tid  = threadIdx.x;
    const int wid  = tid >> 5;
    const int lane = tid & 31;
    const int wm   = wid & 3;      // warp m index: 4 x 32 rows
    const int wn   = wid >> 2;     // warp n index: 2 x 64 cols
    const int m0   = blockIdx.y * 128;
    const int c0   = blockIdx.x * 128;

    // ---- load + split-convert: fp32 [128x128] -> (hi, lo) bf16 tiles -------
#pragma unroll 4
    for (int i = 0; i < 32; ++i) {
        int p = tid + 256 * i;
        uint32_t row = (uint32_t)p >> 6, pk = (uint32_t)p & 63;
        uint32_t off = sw_off(row, pk);
        {   // feat
            int gm = m0 + (int)row;
            float2 v = (gm < B)
                ? *reinterpret_cast<const float2*>(feat + (size_t)gm * 128 + pk * 2)
                : make_float2(0.f, 0.f);
            __nv_bfloat16 h0 = __float2bfloat16(v.x), h1 = __float2bfloat16(v.y);
            __nv_bfloat16 l0 = __float2bfloat16(v.x - __bfloat162float(h0));
            __nv_bfloat16 l1 = __float2bfloat16(v.y - __bfloat162float(h1));
            *reinterpret_cast<uint32_t*>(smem + OF_FHI + off) =
                (uint32_t)__bfloat16_as_ushort(h0) |
                ((uint32_t)__bfloat16_as_ushort(h1) << 16);
            *reinterpret_cast<uint32_t*>(smem + OF_FLO + off) =
                (uint32_t)__bfloat16_as_ushort(l0) |
                ((uint32_t)__bfloat16_as_ushort(l1) << 16);
        }
        {   // W
            int gc = c0 + (int)row;
            float2 v = (gc < C)
                ? *reinterpret_cast<const float2*>(W + (size_t)gc * 128 + pk * 2)
                : make_float2(0.f, 0.f);
            __nv_bfloat16 h0 = __float2bfloat16(v.x), h1 = __float2bfloat16(v.y);
            __nv_bfloat16 l0 = __float2bfloat16(v.x - __bfloat162float(h0));
            __nv_bfloat16 l1 = __float2bfloat16(v.y - __bfloat162float(h1));
            *reinterpret_cast<uint32_t*>(smem + OF_WHI + off) =
                (uint32_t)__bfloat16_as_ushort(h0) |
                ((uint32_t)__bfloat16_as_ushort(h1) << 16);
            *reinterpret_cast<uint32_t*>(smem + OF_WLO + off) =
                (uint32_t)__bfloat16_as_ushort(l0) |
                ((uint32_t)__bfloat16_as_ushort(l1) << 16);
        }
    }
    if (tid < 128) invw_s[tid] = (c0 + tid < C) ? g_invnw[c0 + tid] : 0.f;
    __syncthreads();

    // ---- MMA mainloop: 3 passes x 8 k16-steps ------------------------------
    float acc[2][8][4];
#pragma unroll
    for (int mi = 0; mi < 2; ++mi)
#pragma unroll
        for (int ni = 0; ni < 8; ++ni)
#pragma unroll
            for (int q = 0; q < 4; ++q) acc[mi][ni][q] = 0.f;

    // per-lane ldmatrix row terms (row = base + lane&15, chunk += lane>>4)
    const uint32_t lrow = lane & 15, lhalf = lane >> 4;
    const uint32_t arow0 = (uint32_t)(wm * 32) + lrow;          // mi=0
    const uint32_t arow1 = arow0 + 16;                          // mi=1
    const uint32_t brow0 = (uint32_t)(wn * 64) + lrow;          // n-pair base

    const uint32_t aOf[3] = {OF_FHI, OF_FHI, OF_FLO};
    const uint32_t bOf[3] = {OF_WHI, OF_WLO, OF_WHI};

#pragma unroll
    for (int pass = 0; pass < 3; ++pass) {
        const uint32_t ab = sb + aOf[pass];
        const uint32_t bb = sb + bOf[pass];
#pragma unroll
        for (int s = 0; s < 8; ++s) {
            const uint32_t ck = (uint32_t)(s * 2) + lhalf;      // 16B chunk
            uint32_t a[2][4];
            ldsm4(a[0], ab + sw_row(arow0, ck));
            ldsm4(a[1], ab + sw_row(arow1, ck));
            uint32_t b[4][4];
#pragma unroll
            for (int np = 0; np < 4; ++np)
                ldsm4(b[np], bb + sw_row(brow0 + np * 16, ck));
#pragma unroll
            for (int mi = 0; mi < 2; ++mi)
#pragma unroll
                for (int ni = 0; ni < 8; ++ni) {
                    const int np = ni >> 1, od = ni & 1;
                    mma16816(acc[mi][ni], a[mi], b[np][od], b[np][od + 2]);
                }
        }
    }

    // ---- epilogue: scale + write 3 planes, fuse gt margin patch ------------
    const size_t BC = (size_t)B * (size_t)C;
    float* __restrict__ outCos = out;
    float* __restrict__ outMrg = out + BC;
    float* __restrict__ outIp  = out + 2 * BC;
    const int colq = (lane & 3) * 2;

#pragma unroll
    for (int mi = 0; mi < 2; ++mi) {
#pragma unroll
        for (int h = 0; h < 2; ++h) {
            const int m = m0 + wm * 32 + mi * 16 + (lane >> 2) + h * 8;
            if (m >= B) continue;
            const float invf = g_invnf[m];
            const int   lab  = label[m];
            const size_t ro  = (size_t)m * (size_t)C;
#pragma unroll
            for (int ni = 0; ni < 8; ++ni) {
                const int lc = wn * 64 + ni * 8 + colq;
                const int gc = c0 + lc;
                if (gc >= C) continue;
                float ipx = acc[mi][ni][2 * h];
                float ipy = acc[mi][ni][2 * h + 1];
                float cvx = ipx * invf * invw_s[lc];
                float cvy = ipy * invf * invw_s[lc + 1];
                float mvx = K_SCALE * cvx;
                float mvy = K_SCALE * cvy;
                if (lab == gc || lab == gc + 1) {
                    float cg = (lab == gc) ? cvx : cvy;
                    float cl = fminf(fmaxf(cg, -1.f), 1.f);
                    float val;
                    if (cg > kTHRESH) {
                        float s = sqrtf(fmaxf(1.f - cl * cl, 0.f));
                        val = cl * kCOS_M - s * kSIN_M;
                    } else {
                        val = cl - 0.5f * kSIN_M;
                    }
                    if (lab == gc) mvx = K_SCALE * val; else mvy = K_SCALE * val;
                }
                if (gc + 1 < C) {
                    *reinterpret_cast<float2*>(outCos + ro + gc) = make_float2(cvx, cvy);
                    *reinterpret_cast<float2*>(outMrg + ro + gc) = make_float2(mvx, mvy);
                    *reinterpret_cast<float2*>(outIp  + ro + gc) = make_float2(ipx, ipy);
                } else {
                    outCos[ro + gc] = cvx;
                    outMrg[ro + gc] = mvx;
                    outIp [ro + gc] = ipx;
                }
            }
        }
    }
}

// ---------------------------------------------------------------------------
extern "C" void kernel_launch(void* const* d_in, const int* in_sizes, int n_in,
                              void* d_out, int out_size) {
    const float* feat  = (const float*)d_in[0];
    const float* W     = (const float*)d_in[1];
    const int*   label = (const int*)d_in[2];
    const int D = 128;
    int B = in_sizes[0] / D;
    int C = in_sizes[1] / D;
    float* out = (float*)d_out;

    dim3 nb(32, 8);
    norm_kernel<<<(B + 7) / 8, nb>>>(feat, B, 0);
    norm_kernel<<<(C + 7) / 8, nb>>>(W, C, 1);   // pre-warms W into L2

    cudaFuncSetAttribute(arcface_mma, cudaFuncAttributeMaxDynamicSharedMemorySize,
                         SMEM_TOTAL);
    dim3 grid((C + 127) / 128, (B + 127) / 128);
    arcface_mma<<<grid, 256, SMEM_TOTAL>>>(feat, W, label, out, B, C);
}

// round 8
// speedup vs baseline: 1.5348x; 1.5348x over previous
#include <cuda_runtime.h>
#include <cuda_bf16.h>
#include <cstdint>

// ---------------------------------------------------------------------------
// ArcFace, warp-MMA edition v2 (base sm_103: mma.sync + ldmatrix).
//   Prep kernel:  fp32 rows -> (hi,lo) bf16 split + inverse norms (persistent)
//   GEMM kernel:  3-pass split-bf16 mma.sync, smem-staged coalesced epilogue,
//                 gt margin patch fused.
//   out[0*B*C..) cos, out[1*B*C..) marginal, out[2*B*C..) innerproduct.
// ---------------------------------------------------------------------------

static __device__ __constant__ float kCOS_M  = 0.8775825618903728f;   // cos(0.5)
static __device__ __constant__ float kSIN_M  = 0.4794255386042030f;   // sin(0.5)
static __device__ __constant__ float kTHRESH = -0.8775825618903728f;  // -cos(0.5)
#define K_SCALE 35.0f

#define MAXB 1024
#define MAXC 100608
__device__ float g_invnf[MAXB];
__device__ float g_invnw[MAXC];
__device__ __nv_bfloat16 g_fhi[MAXB * 128];
__device__ __nv_bfloat16 g_flo[MAXB * 128];
__device__ __nv_bfloat16 g_whi[MAXC * 128];
__device__ __nv_bfloat16 g_wlo[MAXC * 128];

// ---------------------------------------------------------------------------
__device__ __forceinline__ uint32_t smem_u32(const void* p) {
    uint32_t a;
    asm("{ .reg .u64 t; cvta.to.shared.u64 t, %1; cvt.u32.u64 %0, t; }"
        : "=r"(a) : "l"(p));
    return a;
}
__device__ __forceinline__ void ldsm4(uint32_t* r, uint32_t addr) {
    asm volatile("ldmatrix.sync.aligned.m8n8.x4.shared.b16 {%0,%1,%2,%3}, [%4];"
                 : "=r"(r[0]), "=r"(r[1]), "=r"(r[2]), "=r"(r[3]) : "r"(addr));
}
__device__ __forceinline__ void mma16816(float* c, const uint32_t* a,
                                         uint32_t b0, uint32_t b1) {
    asm volatile(
        "mma.sync.aligned.m16n8k16.row.col.f32.bf16.bf16.f32 "
        "{%0,%1,%2,%3}, {%4,%5,%6,%7}, {%8,%9}, {%0,%1,%2,%3};"
        : "+f"(c[0]), "+f"(c[1]), "+f"(c[2]), "+f"(c[3])
        : "r"(a[0]), "r"(a[1]), "r"(a[2]), "r"(a[3]), "r"(b0), "r"(b1));
}
// tile row address: row r (256B rows), 16B chunk c (0..15), XOR swizzle
__device__ __forceinline__ uint32_t sw_row(uint32_t r, uint32_t c) {
    return r * 256u + ((c ^ (r & 7)) << 4);
}

// smem: 4 bf16 tiles (32KB each) reused as fp32 ip plane after mainloop,
// aux region (invw/invf/labels) above.
#define OF_FHI 0
#define OF_FLO 32768
#define OF_WHI 65536
#define OF_WLO 98304
#define OF_INVW 131072
#define OF_INVF 131584
#define OF_LAB  132096
#define SMEM_TOTAL 133120
#define IP_PITCH 132          // fp32 plane pitch (pad 4)

// ---------------------------------------------------------------------------
// prep: per row (warp): inverse norm + split fp32 -> hi/lo bf16
// which==0 -> feat arrays, which==1 -> W arrays
// ---------------------------------------------------------------------------
__global__ void prep_kernel(const float* __restrict__ x, int rows, int which) {
    int row = blockIdx.x * 8 + (threadIdx.x >> 5);
    if (row >= rows) return;
    int lane = threadIdx.x & 31;
    float4 v = *reinterpret_cast<const float4*>(x + (size_t)row * 128 + lane * 4);
    float s = v.x * v.x + v.y * v.y + v.z * v.z + v.w * v.w;
#pragma unroll
    for (int o = 16; o > 0; o >>= 1) s += __shfl_xor_sync(0xffffffffu, s, o);
    float inv = rsqrtf(s);
    if (lane == 0) { if (which) g_invnw[row] = inv; else g_invnf[row] = inv; }

    float f[4] = {v.x, v.y, v.z, v.w};
    uint32_t hi[2], lo[2];
#pragma unroll
    for (int q = 0; q < 2; ++q) {
        __nv_bfloat16 h0 = __float2bfloat16(f[2 * q]);
        __nv_bfloat16 h1 = __float2bfloat16(f[2 * q + 1]);
        __nv_bfloat16 l0 = __float2bfloat16(f[2 * q] - __bfloat162float(h0));
        __nv_bfloat16 l1 = __float2bfloat16(f[2 * q + 1] - __bfloat162float(h1));
        hi[q] = (uint32_t)__bfloat16_as_ushort(h0) |
                ((uint32_t)__bfloat16_as_ushort(h1) << 16);
        lo[q] = (uint32_t)__bfloat16_as_ushort(l0) |
                ((uint32_t)__bfloat16_as_ushort(l1) << 16);
    }
    __nv_bfloat16* dhi = which ? g_whi : g_fhi;
    __nv_bfloat16* dlo = which ? g_wlo : g_flo;
    reinterpret_cast<uint2*>(dhi + (size_t)row * 128)[lane] = make_uint2(hi[0], hi[1]);
    reinterpret_cast<uint2*>(dlo + (size_t)row * 128)[lane] = make_uint2(lo[0], lo[1]);
}

// ---------------------------------------------------------------------------
__global__ __launch_bounds__(512, 1)
void arcface_mma(const int* __restrict__ label, float* __restrict__ out,
                 int B, int C) {
    extern __shared__ __align__(1024) char smem[];
    const uint32_t sb = smem_u32(smem);
    float* invw_s = reinterpret_cast<float*>(smem + OF_INVW);
    float* invf_s = reinterpret_cast<float*>(smem + OF_INVF);
    int*   lab_s  = reinterpret_cast<int*>(smem + OF_LAB);

    const int tid  = threadIdx.x;
    const int wid  = tid >> 5;
    const int lane = tid & 31;
    const int wm   = wid & 3;       // 4 warp-rows x 32
    const int wn   = wid >> 2;      // 4 warp-cols x 32
    const int m0   = blockIdx.y * 128;
    const int c0   = blockIdx.x * 128;

    // ---- load bf16 tiles (pre-split in prep kernel), 16B chunks ------------
    const uint4 zero4 = make_uint4(0, 0, 0, 0);
#pragma unroll
    for (int i = 0; i < 4; ++i) {
        int idx = tid + 512 * i;                 // 0..2047
        uint32_t row = (uint32_t)idx >> 4, ck = (uint32_t)idx & 15;
        uint32_t so = sw_row(row, ck);
        int gm = m0 + (int)row;
        int gc = c0 + (int)row;
        uint4 vfh = zero4, vfl = zero4, vwh = zero4, vwl = zero4;
        if (gm < B) {
            vfh = reinterpret_cast<const uint4*>(g_fhi + (size_t)gm * 128)[ck];
            vfl = reinterpret_cast<const uint4*>(g_flo + (size_t)gm * 128)[ck];
        }
        if (gc < C) {
            vwh = reinterpret_cast<const uint4*>(g_whi + (size_t)gc * 128)[ck];
            vwl = reinterpret_cast<const uint4*>(g_wlo + (size_t)gc * 128)[ck];
        }
        *reinterpret_cast<uint4*>(smem + OF_FHI + so) = vfh;
        *reinterpret_cast<uint4*>(smem + OF_FLO + so) = vfl;
        *reinterpret_cast<uint4*>(smem + OF_WHI + so) = vwh;
        *reinterpret_cast<uint4*>(smem + OF_WLO + so) = vwl;
    }
    if (tid < 128)      invw_s[tid] = (c0 + tid < C) ? g_invnw[c0 + tid] : 0.f;
    else if (tid < 256) invf_s[tid - 128] = (m0 + tid - 128 < B) ? g_invnf[m0 + tid - 128] : 0.f;
    else if (tid < 384) lab_s[tid - 256] = (m0 + tid - 256 < B) ? label[m0 + tid - 256] : -1;
    __syncthreads();

    // ---- mainloop: 3 passes x 8 k16-steps ----------------------------------
    float acc[2][4][4];
#pragma unroll
    for (int mi = 0; mi < 2; ++mi)
#pragma unroll
        for (int ni = 0; ni < 4; ++ni)
#pragma unroll
            for (int q = 0; q < 4; ++q) acc[mi][ni][q] = 0.f;

    const uint32_t lrow = lane & 15, lhalf = lane >> 4;
    const uint32_t arow0 = (uint32_t)(wm * 32) + lrow;
    const uint32_t arow1 = arow0 + 16;
    const uint32_t brow0 = (uint32_t)(wn * 32) + lrow;

    const uint32_t aOf[3] = {OF_FHI, OF_FHI, OF_FLO};
    const uint32_t bOf[3] = {OF_WHI, OF_WLO, OF_WHI};

#pragma unroll
    for (int pass = 0; pass < 3; ++pass) {
        const uint32_t ab = sb + aOf[pass];
        const uint32_t bb = sb + bOf[pass];
#pragma unroll
        for (int s = 0; s < 8; ++s) {
            const uint32_t ck = (uint32_t)(s * 2) + lhalf;
            uint32_t a[2][4], b[2][4];
            ldsm4(a[0], ab + sw_row(arow0, ck));
            ldsm4(a[1], ab + sw_row(arow1, ck));
            ldsm4(b[0], bb + sw_row(brow0, ck));
            ldsm4(b[1], bb + sw_row(brow0 + 16, ck));
#pragma unroll
            for (int mi = 0; mi < 2; ++mi)
#pragma unroll
                for (int ni = 0; ni < 4; ++ni) {
                    const int np = ni >> 1, od = ni & 1;
                    mma16816(acc[mi][ni], a[mi], b[np][od], b[np][od + 2]);
                }
        }
    }

    // ---- stage ip plane to smem (reuse tile region) ------------------------
    __syncthreads();                      // all warps done reading tiles
    float* ipS = reinterpret_cast<float*>(smem);
#pragma unroll
    for (int mi = 0; mi < 2; ++mi)
#pragma unroll
        for (int h = 0; h < 2; ++h) {
            int r = wm * 32 + mi * 16 + (lane >> 2) + h * 8;
#pragma unroll
            for (int ni = 0; ni < 4; ++ni) {
                int cc = wn * 32 + ni * 8 + (lane & 3) * 2;
                *reinterpret_cast<float2*>(&ipS[r * IP_PITCH + cc]) =
                    make_float2(acc[mi][ni][2 * h], acc[mi][ni][2 * h + 1]);
            }
        }
    __syncthreads();

    // ---- coalesced write-out: warp per row, lane per 4 columns -------------
    const size_t BC = (size_t)B * (size_t)C;
    float* __restrict__ outCos = out;
    float* __restrict__ outMrg = out + BC;
    float* __restrict__ outIp  = out + 2 * BC;
    const int gc = c0 + lane * 4;
    const float4 invw4 = (gc + 4 <= C)
        ? *reinterpret_cast<const float4*>(&invw_s[lane * 4])
        : make_float4(0.f, 0.f, 0.f, 0.f);

#pragma unroll
    for (int it = 0; it < 8; ++it) {
        const int r = it * 16 + wid;
        const int m = m0 + r;
        if (m >= B) continue;
        float4 ip = *reinterpret_cast<const float4*>(&ipS[r * IP_PITCH + lane * 4]);
        const float invf = invf_s[r];
        float4 cv = make_float4(ip.x * invf * invw4.x, ip.y * invf * invw4.y,
                                ip.z * invf * invw4.z, ip.w * invf * invw4.w);
        float4 mv = make_float4(K_SCALE * cv.x, K_SCALE * cv.y,
                                K_SCALE * cv.z, K_SCALE * cv.w);
        const int lab = lab_s[r];
        if ((unsigned)(lab - gc) < 4u) {
            float cg = (&cv.x)[lab - gc];
            float cl = fminf(fmaxf(cg, -1.f), 1.f);
            float val;
            if (cg > kTHRESH) {
                float s = sqrtf(fmaxf(1.f - cl * cl, 0.f));
                val = cl * kCOS_M - s * kSIN_M;
            } else {
                val = cl - 0.5f * kSIN_M;
            }
            (&mv.x)[lab - gc] = K_SCALE * val;
        }
        const size_t ro = (size_t)m * (size_t)C;
        if (gc + 4 <= C) {
            *reinterpret_cast<float4*>(outCos + ro + gc) = cv;
            *reinterpret_cast<float4*>(outMrg + ro + gc) = mv;
            *reinterpret_cast<float4*>(outIp  + ro + gc) = ip;
        } else if (gc < C) {
            for (int q = 0; q < 4 && gc + q < C; ++q) {
                outCos[ro + gc + q] = (&cv.x)[q];
                outMrg[ro + gc + q] = (&mv.x)[q];
                outIp [ro + gc + q] = (&ip.x)[q];
            }
        }
    }
}

// ---------------------------------------------------------------------------
extern "C" void kernel_launch(void* const* d_in, const int* in_sizes, int n_in,
                              void* d_out, int out_size) {
    const float* feat  = (const float*)d_in[0];
    const float* W     = (const float*)d_in[1];
    const int*   label = (const int*)d_in[2];
    const int D = 128;
    int B = in_sizes[0] / D;
    int C = in_sizes[1] / D;
    float* out = (float*)d_out;

    prep_kernel<<<(B + 7) / 8, 256>>>(feat, B, 0);
    prep_kernel<<<(C + 7) / 8, 256>>>(W, C, 1);

    cudaFuncSetAttribute(arcface_mma, cudaFuncAttributeMaxDynamicSharedMemorySize,
                         SMEM_TOTAL);
    dim3 grid((C + 127) / 128, (B + 127) / 128);
    arcface_mma<<<grid, 512, SMEM_TOTAL>>>(label, out, B, C);
}

// round 9
// speedup vs baseline: 2.3950x; 1.5604x over previous
#include <cuda_runtime.h>
#include <cuda_bf16.h>
#include <cstdint>

// ---------------------------------------------------------------------------
// ArcFace, warp-MMA edition v3 (base sm_103: mma.sync + ldmatrix + cp.async).
//   prep:  fp32 rows -> (hi,lo) bf16 split + inverse norms (persistent)
//   gemm:  BM=128 x BN=64 tiles, 96KB smem -> 2 CTAs/SM, cp.async fills,
//          3-pass split-bf16 mma.sync, smem-staged coalesced epilogue,
//          gt margin patch fused.
// ---------------------------------------------------------------------------

static __device__ __constant__ float kCOS_M  = 0.8775825618903728f;   // cos(0.5)
static __device__ __constant__ float kSIN_M  = 0.4794255386042030f;   // sin(0.5)
static __device__ __constant__ float kTHRESH = -0.8775825618903728f;  // -cos(0.5)
#define K_SCALE 35.0f

#define MAXB 1024
#define MAXC 100608
__device__ float g_invnf[MAXB];
__device__ float g_invnw[MAXC];
__device__ __nv_bfloat16 g_fhi[MAXB * 128];
__device__ __nv_bfloat16 g_flo[MAXB * 128];
__device__ __nv_bfloat16 g_whi[(size_t)MAXC * 128];
__device__ __nv_bfloat16 g_wlo[(size_t)MAXC * 128];

// ---------------------------------------------------------------------------
__device__ __forceinline__ uint32_t smem_u32(const void* p) {
    uint32_t a;
    asm("{ .reg .u64 t; cvta.to.shared.u64 t, %1; cvt.u32.u64 %0, t; }"
        : "=r"(a) : "l"(p));
    return a;
}
__device__ __forceinline__ void cp16(uint32_t dst, const void* src, uint32_t nbytes) {
    asm volatile("cp.async.cg.shared.global [%0], [%1], 16, %2;"
                 :: "r"(dst), "l"(src), "r"(nbytes));
}
__device__ __forceinline__ void cp_wait_all() {
    asm volatile("cp.async.wait_all;" ::: "memory");
}
__device__ __forceinline__ void ldsm4(uint32_t* r, uint32_t addr) {
    asm volatile("ldmatrix.sync.aligned.m8n8.x4.shared.b16 {%0,%1,%2,%3}, [%4];"
                 : "=r"(r[0]), "=r"(r[1]), "=r"(r[2]), "=r"(r[3]) : "r"(addr));
}
__device__ __forceinline__ void mma16816(float* c, const uint32_t* a,
                                         uint32_t b0, uint32_t b1) {
    asm volatile(
        "mma.sync.aligned.m16n8k16.row.col.f32.bf16.bf16.f32 "
        "{%0,%1,%2,%3}, {%4,%5,%6,%7}, {%8,%9}, {%0,%1,%2,%3};"
        : "+f"(c[0]), "+f"(c[1]), "+f"(c[2]), "+f"(c[3])
        : "r"(a[0]), "r"(a[1]), "r"(a[2]), "r"(a[3]), "r"(b0), "r"(b1));
}
// tile row address: row r (256B rows), 16B chunk c (0..15), XOR swizzle
__device__ __forceinline__ uint32_t sw_row(uint32_t r, uint32_t c) {
    return r * 256u + ((c ^ (r & 7)) << 4);
}

// smem layout (96KB tiles + aux). ip plane reuses f region after mainloop.
#define OF_FHI 0
#define OF_FLO 32768
#define OF_WHI 65536
#define OF_WLO 81920
#define OF_INVW 98304           // 64 floats
#define OF_INVF 98560           // 128 floats
#define OF_LAB  99072           // 128 ints
#define SMEM_TOTAL 99584
#define IP_PITCH 68             // fp32 plane pitch (64 + 4 pad)

// ---------------------------------------------------------------------------
__global__ void prep_kernel(const float* __restrict__ x, int rows, int which) {
    int row = blockIdx.x * 8 + (threadIdx.x >> 5);
    if (row >= rows) return;
    int lane = threadIdx.x & 31;
    float4 v = *reinterpret_cast<const float4*>(x + (size_t)row * 128 + lane * 4);
    float s = v.x * v.x + v.y * v.y + v.z * v.z + v.w * v.w;
#pragma unroll
    for (int o = 16; o > 0; o >>= 1) s += __shfl_xor_sync(0xffffffffu, s, o);
    float inv = rsqrtf(s);
    if (lane == 0) { if (which) g_invnw[row] = inv; else g_invnf[row] = inv; }

    float f[4] = {v.x, v.y, v.z, v.w};
    uint32_t hi[2], lo[2];
#pragma unroll
    for (int q = 0; q < 2; ++q) {
        __nv_bfloat16 h0 = __float2bfloat16(f[2 * q]);
        __nv_bfloat16 h1 = __float2bfloat16(f[2 * q + 1]);
        __nv_bfloat16 l0 = __float2bfloat16(f[2 * q] - __bfloat162float(h0));
        __nv_bfloat16 l1 = __float2bfloat16(f[2 * q + 1] - __bfloat162float(h1));
        hi[q] = (uint32_t)__bfloat16_as_ushort(h0) |
                ((uint32_t)__bfloat16_as_ushort(h1) << 16);
        lo[q] = (uint32_t)__bfloat16_as_ushort(l0) |
                ((uint32_t)__bfloat16_as_ushort(l1) << 16);
    }
    __nv_bfloat16* dhi = which ? g_whi : g_fhi;
    __nv_bfloat16* dlo = which ? g_wlo : g_flo;
    reinterpret_cast<uint2*>(dhi + (size_t)row * 128)[lane] = make_uint2(hi[0], hi[1]);
    reinterpret_cast<uint2*>(dlo + (size_t)row * 128)[lane] = make_uint2(lo[0], lo[1]);
}

// ---------------------------------------------------------------------------
__global__ __launch_bounds__(256, 2)
void arcface_mma(const int* __restrict__ label, float* __restrict__ out,
                 int B, int C) {
    extern __shared__ __align__(1024) char smem[];
    const uint32_t sb = smem_u32(smem);
    float* invw_s = reinterpret_cast<float*>(smem + OF_INVW);
    float* invf_s = reinterpret_cast<float*>(smem + OF_INVF);
    int*   lab_s  = reinterpret_cast<int*>(smem + OF_LAB);

    const int tid  = threadIdx.x;
    const int wid  = tid >> 5;
    const int lane = tid & 31;
    const int wm   = wid & 3;       // 4 warp-rows x 32
    const int wn   = wid >> 2;      // 2 warp-cols x 32
    const int m0   = blockIdx.x * 128;   // m in grid.x: W-sharing CTAs adjacent
    const int c0   = blockIdx.y * 64;

    // ---- async tile fills (pre-split bf16 from prep kernel) ----------------
#pragma unroll
    for (int i = 0; i < 8; ++i) {                 // feat: 2048 chunks / tile pair
        int idx = tid + 256 * i;
        uint32_t row = (uint32_t)idx >> 4, ck = (uint32_t)idx & 15;
        uint32_t so = sw_row(row, ck);
        int gm = m0 + (int)row;
        uint32_t ok = (gm < B) ? 16u : 0u;
        int gs = (gm < B) ? gm : 0;
        cp16(sb + OF_FHI + so, reinterpret_cast<const char*>(g_fhi) + ((size_t)gs * 256 + ck * 16), ok);
        cp16(sb + OF_FLO + so, reinterpret_cast<const char*>(g_flo) + ((size_t)gs * 256 + ck * 16), ok);
    }
#pragma unroll
    for (int i = 0; i < 4; ++i) {                 // W: 1024 chunks / tile pair
        int idx = tid + 256 * i;
        uint32_t row = (uint32_t)idx >> 4, ck = (uint32_t)idx & 15;
        uint32_t so = sw_row(row, ck);
        int gc = c0 + (int)row;
        uint32_t ok = (gc < C) ? 16u : 0u;
        int gs = (gc < C) ? gc : 0;
        cp16(sb + OF_WHI + so, reinterpret_cast<const char*>(g_whi) + ((size_t)gs * 256 + ck * 16), ok);
        cp16(sb + OF_WLO + so, reinterpret_cast<const char*>(g_wlo) + ((size_t)gs * 256 + ck * 16), ok);
    }
    if (tid < 64)       invw_s[tid] = (c0 + tid < C) ? g_invnw[c0 + tid] : 0.f;
    else if (tid < 192) invf_s[tid - 64] = (m0 + tid - 64 < B) ? g_invnf[m0 + tid - 64] : 0.f;
    else if (tid < 320 && tid >= 192) {}
    if (tid >= 128 && tid < 256) lab_s[tid - 128] = (m0 + tid - 128 < B) ? label[m0 + tid - 128] : -1;
    cp_wait_all();
    __syncthreads();

    // ---- mainloop: 3 passes x 8 k16-steps ----------------------------------
    float acc[2][4][4];
#pragma unroll
    for (int mi = 0; mi < 2; ++mi)
#pragma unroll
        for (int ni = 0; ni < 4; ++ni)
#pragma unroll
            for (int q = 0; q < 4; ++q) acc[mi][ni][q] = 0.f;

    const uint32_t lrow = lane & 15, lhalf = lane >> 4;
    const uint32_t arow0 = (uint32_t)(wm * 32) + lrow;
    const uint32_t arow1 = arow0 + 16;
    const uint32_t brow0 = (uint32_t)(wn * 32) + lrow;

    const uint32_t aOf[3] = {OF_FHI, OF_FHI, OF_FLO};
    const uint32_t bOf[3] = {OF_WHI, OF_WLO, OF_WHI};

#pragma unroll
    for (int pass = 0; pass < 3; ++pass) {
        const uint32_t ab = sb + aOf[pass];
        const uint32_t bb = sb + bOf[pass];
#pragma unroll
        for (int s = 0; s < 8; ++s) {
            const uint32_t ck = (uint32_t)(s * 2) + lhalf;
            uint32_t a[2][4], b[2][4];
            ldsm4(a[0], ab + sw_row(arow0, ck));
            ldsm4(a[1], ab + sw_row(arow1, ck));
            ldsm4(b[0], bb + sw_row(brow0, ck));
            ldsm4(b[1], bb + sw_row(brow0 + 16, ck));
#pragma unroll
            for (int mi = 0; mi < 2; ++mi)
#pragma unroll
                for (int ni = 0; ni < 4; ++ni) {
                    const int np = ni >> 1, od = ni & 1;
                    mma16816(acc[mi][ni], a[mi], b[np][od], b[np][od + 2]);
                }
        }
    }

    // ---- stage ip plane to smem (reuse f-tile region) ----------------------
    __syncthreads();
    float* ipS = reinterpret_cast<float*>(smem);
#pragma unroll
    for (int mi = 0; mi < 2; ++mi)
#pragma unroll
        for (int h = 0; h < 2; ++h) {
            int r = wm * 32 + mi * 16 + (lane >> 2) + h * 8;
#pragma unroll
            for (int ni = 0; ni < 4; ++ni) {
                int cc = wn * 32 + ni * 8 + (lane & 3) * 2;
                *reinterpret_cast<float2*>(&ipS[r * IP_PITCH + cc]) =
                    make_float2(acc[mi][ni][2 * h], acc[mi][ni][2 * h + 1]);
            }
        }
    __syncthreads();

    // ---- coalesced write-out: warp -> 2 rows/iter, 16 lanes x float4 -------
    const size_t BC = (size_t)B * (size_t)C;
    float* __restrict__ outCos = out;
    float* __restrict__ outMrg = out + BC;
    float* __restrict__ outIp  = out + 2 * BC;
    const int lh  = lane >> 4;              // row half
    const int lc4 = (lane & 15) * 4;        // column (0..60)
    const int gc  = c0 + lc4;
    const float4 invw4 = (gc + 4 <= C)
        ? *reinterpret_cast<const float4*>(&invw_s[lc4])
        : make_float4(0.f, 0.f, 0.f, 0.f);

#pragma unroll
    for (int it = 0; it < 8; ++it) {
        const int r = it * 16 + wid * 2 + lh;
        const int m = m0 + r;
        if (m >= B) continue;
        float4 ip = *reinterpret_cast<const float4*>(&ipS[r * IP_PITCH + lc4]);
        const float invf = invf_s[r];
        float4 cv = make_float4(ip.x * invf * invw4.x, ip.y * invf * invw4.y,
                                ip.z * invf * invw4.z, ip.w * invf * invw4.w);
        float4 mv = make_float4(K_SCALE * cv.x, K_SCALE * cv.y,
                                K_SCALE * cv.z, K_SCALE * cv.w);
        const int lab = lab_s[r];
        if ((unsigned)(lab - gc) < 4u) {
            float cg = (&cv.x)[lab - gc];
            float cl = fminf(fmaxf(cg, -1.f), 1.f);
            float val;
            if (cg > kTHRESH) {
                float s = sqrtf(fmaxf(1.f - cl * cl, 0.f));
                val = cl * kCOS_M - s * kSIN_M;
            } else {
                val = cl - 0.5f * kSIN_M;
            }
            (&mv.x)[lab - gc] = K_SCALE * val;
        }
        const size_t ro = (size_t)m * (size_t)C;
        if (gc + 4 <= C) {
            *reinterpret_cast<float4*>(outCos + ro + gc) = cv;
            *reinterpret_cast<float4*>(outMrg + ro + gc) = mv;
            *reinterpret_cast<float4*>(outIp  + ro + gc) = ip;
        } else if (gc < C) {
            for (int q = 0; q < 4 && gc + q < C; ++q) {
                outCos[ro + gc + q] = (&cv.x)[q];
                outMrg[ro + gc + q] = (&mv.x)[q];
                outIp [ro + gc + q] = (&ip.x)[q];
            }
        }
    }
}

// ---------------------------------------------------------------------------
extern "C" void kernel_launch(void* const* d_in, const int* in_sizes, int n_in,
                              void* d_out, int out_size) {
    const float* feat  = (const float*)d_in[0];
    const float* W     = (const float*)d_in[1];
    const int*   label = (const int*)d_in[2];
    const int D = 128;
    int B = in_sizes[0] / D;
    int C = in_sizes[1] / D;
    float* out = (float*)d_out;

    prep_kernel<<<(B + 7) / 8, 256>>>(feat, B, 0);
    prep_kernel<<<(C + 7) / 8, 256>>>(W, C, 1);

    cudaFuncSetAttribute(arcface_mma, cudaFuncAttributeMaxDynamicSharedMemorySize,
                         SMEM_TOTAL);
    dim3 grid((B + 127) / 128, (C + 63) / 64);   // m in x -> W-sharing CTAs adjacent
    arcface_mma<<<grid, 256, SMEM_TOTAL>>>(label, out, B, C);
}